// round 5
// baseline (speedup 1.0000x reference)
#include <cuda_runtime.h>
#include <cuda_bf16.h>
#include <math.h>

// ---------------------------------------------------------------------------
// InstantNGP hash-grid embedding, 16 levels, F=2, T=2^19, 1M points.
//
// R5 = R3 load structure (8 flat independent float2 gathers per level — the
// pair-load/select experiment of R4 doubled the per-level dependent-load
// critical path and regressed 2x) plus:
//  * smem-staged coalesced output (no r[16] reg array: regs ~57 -> ~40,
//    occupancy 45% -> ~70%; store wavefronts 256 -> 32 per warp)
//  * per-level __syncthreads() only for levels 0..4 (the L1-resident zone,
//    res<=40). For fine levels the barrier is pure serialization; dropping
//    it lets ptxas overlap gathers across unrolled levels (MLP ~8 -> ~16).
// ---------------------------------------------------------------------------

#define NLVL 16
#define LOG2_T 19
#define TABLE_SIZE (1u << LOG2_T)
#define HMASK (TABLE_SIZE - 1u)
#define BSZ 1048576
#define PRIME1 2654435761u
#define PRIME2 805459861u
#define TPB 256
#define SROW 34   // floats per smem row (32 data + 2 pad)

struct LevelParams {
    float invgs;   // 1 / grid_size (host-computed via double)
    float resm1;   // (float)(res - 1)
};
struct AllParams {
    LevelParams lp[NLVL];
};

__global__ __launch_bounds__(TPB)
void hash_embed_kernel(const float* __restrict__ x,
                       const float* __restrict__ emb,
                       float* __restrict__ out,
                       AllParams P)
{
    __shared__ float s[TPB * SROW];

    const int tid = threadIdx.x;
    const int p = blockIdx.x * TPB + tid;      // BSZ % TPB == 0

    const float x0 = __ldg(&x[p * 3 + 0]);
    const float x1 = __ldg(&x[p * 3 + 1]);
    const float x2 = __ldg(&x[p * 3 + 2]);

    float* srow = &s[tid * SROW];

#pragma unroll
    for (int l = 0; l < NLVL; ++l) {
        const float invgs = P.lp[l].invgs;
        const float rm1   = P.lp[l].resm1;

        const float rel0 = (x0 + 1.0f) * invgs;
        const float rel1 = (x1 + 1.0f) * invgs;
        const float rel2 = (x2 + 1.0f) * invgs;

        const float f0 = fminf(fmaxf(floorf(rel0), 0.0f), rm1);
        const float f1 = fminf(fmaxf(floorf(rel1), 0.0f), rm1);
        const float f2 = fminf(fmaxf(floorf(rel2), 0.0f), rm1);

        const float w0 = rel0 - f0;
        const float w1 = rel1 - f1;
        const float w2 = rel2 - f2;

        const unsigned u0 = (unsigned)f0;
        const unsigned u1 = (unsigned)f1;
        const unsigned u2 = (unsigned)f2;

        const unsigned a0 = u0;             // dim0 prime = 1
        const unsigned a1 = u0 + 1u;
        const unsigned b0 = u1 * PRIME1;
        const unsigned b1 = b0 + PRIME1;
        const unsigned c0 = u2 * PRIME2;
        const unsigned c1 = c0 + PRIME2;

        const float2* __restrict__ tab =
            (const float2*)emb + (size_t)l * TABLE_SIZE;

        const unsigned h000 = (a0 ^ b0 ^ c0) & HMASK;
        const unsigned h100 = (a1 ^ b0 ^ c0) & HMASK;
        const unsigned h010 = (a0 ^ b1 ^ c0) & HMASK;
        const unsigned h110 = (a1 ^ b1 ^ c0) & HMASK;
        const unsigned h001 = (a0 ^ b0 ^ c1) & HMASK;
        const unsigned h101 = (a1 ^ b0 ^ c1) & HMASK;
        const unsigned h011 = (a0 ^ b1 ^ c1) & HMASK;
        const unsigned h111 = (a1 ^ b1 ^ c1) & HMASK;

        // 8 independent gathers, one latency round
        const float2 v000 = __ldg(&tab[h000]);
        const float2 v100 = __ldg(&tab[h100]);
        const float2 v010 = __ldg(&tab[h010]);
        const float2 v110 = __ldg(&tab[h110]);
        const float2 v001 = __ldg(&tab[h001]);
        const float2 v101 = __ldg(&tab[h101]);
        const float2 v011 = __ldg(&tab[h011]);
        const float2 v111 = __ldg(&tab[h111]);

        const float m0 = 1.0f - w0;
        const float m1 = 1.0f - w1;
        const float m2 = 1.0f - w2;

        const float p00 = m1 * m2;
        const float p10 = w1 * m2;
        const float p01 = m1 * w2;
        const float p11 = w1 * w2;

        const float wt000 = m0 * p00;
        const float wt100 = w0 * p00;
        const float wt010 = m0 * p10;
        const float wt110 = w0 * p10;
        const float wt001 = m0 * p01;
        const float wt101 = w0 * p01;
        const float wt011 = m0 * p11;
        const float wt111 = w0 * p11;

        float accx = wt000 * v000.x;
        float accy = wt000 * v000.y;
        accx = fmaf(wt100, v100.x, accx);
        accy = fmaf(wt100, v100.y, accy);
        accx = fmaf(wt010, v010.x, accx);
        accy = fmaf(wt010, v010.y, accy);
        accx = fmaf(wt110, v110.x, accx);
        accy = fmaf(wt110, v110.y, accy);
        accx = fmaf(wt001, v001.x, accx);
        accy = fmaf(wt001, v001.y, accy);
        accx = fmaf(wt101, v101.x, accx);
        accy = fmaf(wt101, v101.y, accy);
        accx = fmaf(wt011, v011.x, accx);
        accy = fmaf(wt011, v011.y, accy);
        accx = fmaf(wt111, v111.x, accx);
        accy = fmaf(wt111, v111.y, accy);

        srow[2 * l]     = accx;
        srow[2 * l + 1] = accy;

        // phase-lock only while the level's table fits in L1 (res <= 40);
        // for fine levels let gathers pipeline across levels instead.
        if (l < 5) __syncthreads();
    }

    __syncthreads();   // guard copy-out (threads read other threads' rows)

    // coalesced copy-out: consecutive lanes read consecutive elements of one
    // point's smem row (banks (34*row + e) % 32 distinct -> conflict-free);
    // each warp's STG.32 covers one contiguous 128B line.
    const int base = blockIdx.x * (TPB * 32);
#pragma unroll
    for (int k = tid; k < TPB * 32; k += TPB) {
        out[base + k] = s[(k >> 5) * SROW + (k & 31)];
    }
}

extern "C" void kernel_launch(void* const* d_in, const int* in_sizes, int n_in,
                              void* d_out, int out_size)
{
    const float* x   = (const float*)d_in[0];   // (1048576, 3) f32
    const float* emb = (const float*)d_in[1];   // (16, 524288, 2) f32
    float* out = (float*)d_out;                 // (1048576, 32) f32

    // Recompute RESOLUTIONS with the reference's double-precision formula
    // (several floor() results sit exactly on integer boundaries).
    AllParams P;
    const double growth = exp((log(512.0) - log(16.0)) / 15.0);
    for (int i = 0; i < NLVL; ++i) {
        int res = (int)floor(16.0 * pow(growth, (double)i));
        float gsf = (float)(2.0 / (double)res);
        P.lp[i].invgs = (float)(1.0 / (double)gsf);
        P.lp[i].resm1 = (float)(res - 1);
    }

    dim3 grid(BSZ / TPB);
    dim3 block(TPB);
    hash_embed_kernel<<<grid, block>>>(x, emb, out, P);
}

// round 8
// speedup vs baseline: 2.4600x; 2.4600x over previous
#include <cuda_runtime.h>
#include <cuda_bf16.h>
#include <math.h>

// ---------------------------------------------------------------------------
// InstantNGP hash-grid embedding, 16 levels, F=2, T=2^19, 1M points.
//
// R6 = R3 (366.7us: full unroll, register accumulators, no smem in loop,
// per-level barrier, direct STG.128 tail) + ONE change: pair-loads.
//
// dim0 prime = 1 ⇒ for even u0 the two x-corners of a cell hash to {h, h^1},
// i.e. one aligned float4 in the table. So per (y,z) combo we always load
// that float4 (covers both corners when u0 even), and issue a *predicated*
// float2 load for the second corner only when u0 is odd (~50% of lanes;
// predicated-off lanes emit no L1 wavefronts). All loads stay independent →
// still ONE latency round per level (the R4 mistake was in-loop smem staging
// that collapsed MLP, not the pair-load concept; R4 > R5 proved that).
// Expected: ~25% fewer L1 load wavefronts; L1 was binding at 87.6%.
// ---------------------------------------------------------------------------

#define NLVL 16
#define LOG2_T 19
#define TABLE_SIZE (1u << LOG2_T)
#define HMASK (TABLE_SIZE - 1u)
#define BSZ 1048576
#define PRIME1 2654435761u
#define PRIME2 805459861u
#define TPB 256

struct LevelParams {
    float invgs;   // 1 / grid_size (host-computed via double)
    float resm1;   // (float)(res - 1)
};
struct AllParams {
    LevelParams lp[NLVL];
};

__global__ __launch_bounds__(TPB)
void hash_embed_kernel(const float* __restrict__ x,
                       const float* __restrict__ emb,
                       float* __restrict__ out,
                       AllParams P)
{
    const int p = blockIdx.x * TPB + threadIdx.x;   // BSZ % TPB == 0

    const float x0 = x[p * 3 + 0];
    const float x1 = x[p * 3 + 1];
    const float x2 = x[p * 3 + 2];

    float2 r[NLVL];

#pragma unroll
    for (int l = 0; l < NLVL; ++l) {
        const float invgs = P.lp[l].invgs;
        const float rm1   = P.lp[l].resm1;

        const float rel0 = (x0 + 1.0f) * invgs;
        const float rel1 = (x1 + 1.0f) * invgs;
        const float rel2 = (x2 + 1.0f) * invgs;

        const float f0 = fminf(fmaxf(floorf(rel0), 0.0f), rm1);
        const float f1 = fminf(fmaxf(floorf(rel1), 0.0f), rm1);
        const float f2 = fminf(fmaxf(floorf(rel2), 0.0f), rm1);

        const float w0 = rel0 - f0;
        const float w1 = rel1 - f1;
        const float w2 = rel2 - f2;

        const unsigned u0 = (unsigned)f0;
        const unsigned u1 = (unsigned)f1;
        const unsigned u2 = (unsigned)f2;

        const bool odd0 = (u0 & 1u) != 0u;

        const unsigned a1 = u0 + 1u;
        const unsigned b0 = u1 * PRIME1;
        const unsigned b1 = b0 + PRIME1;
        const unsigned c0 = u2 * PRIME2;
        const unsigned c1 = c0 + PRIME2;

        const float2* __restrict__ tab =
            (const float2*)emb + (size_t)l * TABLE_SIZE;
        const float4* __restrict__ tab4 = (const float4*)tab;

        // x-corner-0 hash per (y,z) combo; for even u0 the pair {h, h^1}
        // holds BOTH x-corners.
        const unsigned h00 = (u0 ^ b0 ^ c0) & HMASK;
        const unsigned h10 = (u0 ^ b1 ^ c0) & HMASK;
        const unsigned h01 = (u0 ^ b0 ^ c1) & HMASK;
        const unsigned h11 = (u0 ^ b1 ^ c1) & HMASK;

        // 4 unconditional float4 pair-loads — independent, one round
        const float4 q00 = __ldg(&tab4[h00 >> 1]);
        const float4 q10 = __ldg(&tab4[h10 >> 1]);
        const float4 q01 = __ldg(&tab4[h01 >> 1]);
        const float4 q11 = __ldg(&tab4[h11 >> 1]);

        // 4 predicated float2 loads for odd u0 — also independent of the
        // float4 results, issue in the SAME round; ~50% of lanes active.
        float2 e00, e10, e01, e11;
        if (odd0) {
            e00 = __ldg(&tab[(a1 ^ b0 ^ c0) & HMASK]);
            e10 = __ldg(&tab[(a1 ^ b1 ^ c0) & HMASK]);
            e01 = __ldg(&tab[(a1 ^ b0 ^ c1) & HMASK]);
            e11 = __ldg(&tab[(a1 ^ b1 ^ c1) & HMASK]);
        } else {
            e00 = e10 = e01 = e11 = make_float2(0.0f, 0.0f);
        }

        const bool o00 = (h00 & 1u) != 0u;
        const bool o10 = (h10 & 1u) != 0u;
        const bool o01 = (h01 & 1u) != 0u;
        const bool o11 = (h11 & 1u) != 0u;

        // corner A (x-bit 0): select the half of the pair addressed by hXX
        const float2 vA00 = o00 ? make_float2(q00.z, q00.w) : make_float2(q00.x, q00.y);
        const float2 vA10 = o10 ? make_float2(q10.z, q10.w) : make_float2(q10.x, q10.y);
        const float2 vA01 = o01 ? make_float2(q01.z, q01.w) : make_float2(q01.x, q01.y);
        const float2 vA11 = o11 ? make_float2(q11.z, q11.w) : make_float2(q11.x, q11.y);

        // corner B (x-bit 1): other half of the pair (even u0) or the
        // predicated load result (odd u0)
        const float2 vB00 = odd0 ? e00 : (o00 ? make_float2(q00.x, q00.y) : make_float2(q00.z, q00.w));
        const float2 vB10 = odd0 ? e10 : (o10 ? make_float2(q10.x, q10.y) : make_float2(q10.z, q10.w));
        const float2 vB01 = odd0 ? e01 : (o01 ? make_float2(q01.x, q01.y) : make_float2(q01.z, q01.w));
        const float2 vB11 = odd0 ? e11 : (o11 ? make_float2(q11.x, q11.y) : make_float2(q11.z, q11.w));

        const float m0 = 1.0f - w0;
        const float m1 = 1.0f - w1;
        const float m2 = 1.0f - w2;

        const float p00 = m1 * m2;
        const float p10 = w1 * m2;
        const float p01 = m1 * w2;
        const float p11 = w1 * w2;

        // blend the two x-corners first, then the (y,z) combos
        const float cx00x = fmaf(w0, vB00.x, m0 * vA00.x);
        const float cx00y = fmaf(w0, vB00.y, m0 * vA00.y);
        const float cx10x = fmaf(w0, vB10.x, m0 * vA10.x);
        const float cx10y = fmaf(w0, vB10.y, m0 * vA10.y);
        const float cx01x = fmaf(w0, vB01.x, m0 * vA01.x);
        const float cx01y = fmaf(w0, vB01.y, m0 * vA01.y);
        const float cx11x = fmaf(w0, vB11.x, m0 * vA11.x);
        const float cx11y = fmaf(w0, vB11.y, m0 * vA11.y);

        float accx = p00 * cx00x;
        float accy = p00 * cx00y;
        accx = fmaf(p10, cx10x, accx);
        accy = fmaf(p10, cx10y, accy);
        accx = fmaf(p01, cx01x, accx);
        accy = fmaf(p01, cx01y, accy);
        accx = fmaf(p11, cx11x, accx);
        accy = fmaf(p11, cx11y, accy);

        r[l].x = accx;
        r[l].y = accy;

        // same phase-locking as R3 (kept identical — it was part of the
        // known-good configuration)
        __syncthreads();
    }

    // each thread writes its own full 128-byte output line (as in R3)
    float4* __restrict__ o = (float4*)(out + (size_t)p * 32);
#pragma unroll
    for (int i = 0; i < 8; ++i) {
        o[i] = make_float4(r[2 * i].x, r[2 * i].y,
                           r[2 * i + 1].x, r[2 * i + 1].y);
    }
}

extern "C" void kernel_launch(void* const* d_in, const int* in_sizes, int n_in,
                              void* d_out, int out_size)
{
    const float* x   = (const float*)d_in[0];   // (1048576, 3) f32
    const float* emb = (const float*)d_in[1];   // (16, 524288, 2) f32
    float* out = (float*)d_out;                 // (1048576, 32) f32

    // Recompute RESOLUTIONS with the reference's double-precision formula
    // (several floor() results sit exactly on integer boundaries).
    AllParams P;
    const double growth = exp((log(512.0) - log(16.0)) / 15.0);
    for (int i = 0; i < NLVL; ++i) {
        int res = (int)floor(16.0 * pow(growth, (double)i));
        float gsf = (float)(2.0 / (double)res);
        P.lp[i].invgs = (float)(1.0 / (double)gsf);
        P.lp[i].resm1 = (float)(res - 1);
    }

    dim3 grid(BSZ / TPB);
    dim3 block(TPB);
    hash_embed_kernel<<<grid, block>>>(x, emb, out, P);
}